// round 17
// baseline (speedup 1.0000x reference)
#include <cuda_runtime.h>
#include <math.h>
#include <stdint.h>

#define HWSZ 25600        // 160*160
#define IMG  614400       // 24*HWSZ  (per-channel size in [B,C,D,H,W])
#define BST  19660800     // 32*IMG   (per-batch stride for C=32 tensors)
#define HBUF 3276800      // 4 images * 32ch * HWSZ (fwd b0,b1 + bwd b0,b1)

// ---------------- scratch (device globals; no allocations) ----------------
__device__ float g_sf1[78643200];        // [2,64,24,160,160]  slice_flow mid
__device__ float g_hist[2][39321600];    // fwd / bwd hidden history [B,C,D,H,W]
__device__ float g_h[2][HBUF];           // ping-pong hidden state, 4 images
__device__ float g_u[HBUF];              // update gate
__device__ float g_rh[HBUF];             // reset*h
__device__ float g_gn[32];               // [b][group][sum,sumsq]
__device__ float g_A[128];               // GN affine scale  [b][64]
__device__ float g_B[128];               // GN affine shift

__device__ __forceinline__ float sigm(float z){ return 1.0f/(1.0f+expf(-z)); }

__device__ __forceinline__ uint32_t tf32cvt(float f){
    uint32_t u; asm("cvt.rna.tf32.f32 %0, %1;" : "=r"(u) : "f"(f)); return u;
}

__device__ __forceinline__ void mma_tf32(float c[4], const uint32_t a[4],
                                         uint32_t b0, uint32_t b1){
    asm volatile(
        "mma.sync.aligned.m16n8k8.row.col.f32.tf32.tf32.f32 "
        "{%0,%1,%2,%3}, {%4,%5,%6,%7}, {%8,%9}, {%0,%1,%2,%3};"
        : "+f"(c[0]), "+f"(c[1]), "+f"(c[2]), "+f"(c[3])
        : "r"(a[0]), "r"(a[1]), "r"(a[2]), "r"(a[3]), "r"(b0), "r"(b1));
}

// ---------------- zero the GN accumulator ----------------
__global__ void k_gz(){ if (threadIdx.x < 32) g_gn[threadIdx.x] = 0.f; }

// ---------------- f1: conv3d over D (32->64) + bias + GN partial sums ----------------
__global__ void __launch_bounds__(256) k_f1(const float* __restrict__ x,
                                            const float* __restrict__ w,
                                            const float* __restrict__ b)
{
    __shared__ float ws[6144];                       // [64oc][32ic][3t]
    int tid = threadIdx.x;
    #pragma unroll 1
    for (int i = tid; i < 6144; i += 256) ws[i] = w[i];
    __syncthreads();

    int n  = blockIdx.y; int bb = n / 24, d = n - bb*24;
    int lane = tid & 31, ocg = tid >> 5;             // ocg == GN group
    int hw0 = blockIdx.x * 256 + lane;

    float acc[8][8];
    #pragma unroll
    for (int j=0;j<8;j++){
        #pragma unroll
        for (int k=0;k<8;k++) acc[j][k]=0.f;
    }
    const float* xb = x + bb*BST;

    #pragma unroll 1
    for (int ic = 0; ic < 32; ic++) {
        float wr[8][3];
        #pragma unroll
        for (int j=0;j<8;j++){
            int oc = ocg*8+j;
            wr[j][0]=ws[oc*96+ic*3+0];
            wr[j][1]=ws[oc*96+ic*3+1];
            wr[j][2]=ws[oc*96+ic*3+2];
        }
        #pragma unroll
        for (int t=0;t<3;t++){
            int dd = d + t - 1;
            if (dd >= 0 && dd < 24){
                const float* xp = xb + ic*IMG + dd*HWSZ + hw0;
                #pragma unroll
                for (int k=0;k<8;k++){
                    float v = __ldg(xp + k*32);
                    #pragma unroll
                    for (int j=0;j<8;j++) acc[j][k] = fmaf(wr[j][t], v, acc[j][k]);
                }
            }
        }
    }

    float s=0.f, ss=0.f;
    #pragma unroll
    for (int j=0;j<8;j++){
        int oc = ocg*8+j;
        float bv = b[oc];
        float* op = g_sf1 + (bb*64+oc)*IMG + d*HWSZ + hw0;
        #pragma unroll
        for (int k=0;k<8;k++){
            float v = acc[j][k] + bv;
            op[k*32] = v;
            s += v; ss = fmaf(v,v,ss);
        }
    }
    #pragma unroll
    for (int o=16;o;o>>=1){
        s  += __shfl_xor_sync(0xffffffffu, s,  o);
        ss += __shfl_xor_sync(0xffffffffu, ss, o);
    }
    if (lane == 0){
        atomicAdd(&g_gn[(bb*8+ocg)*2+0], s);
        atomicAdd(&g_gn[(bb*8+ocg)*2+1], ss);
    }
}

// ---------------- GN finalize ----------------
__global__ void k_gnfin(const float* __restrict__ gg, const float* __restrict__ gb)
{
    int c = threadIdx.x;                 // 0..127
    int bb = c >> 6, ch = c & 63, g = ch >> 3;
    const float N = 4915200.f;           // 8ch * 24 * 160 * 160
    float s  = g_gn[(bb*8+g)*2+0];
    float ss = g_gn[(bb*8+g)*2+1];
    float mu  = s / N;
    float var = ss / N - mu*mu;
    float A = gg[ch] * rsqrtf(var + 1e-5f);
    g_A[c] = A;
    g_B[c] = gb[ch] - mu * A;
}

// ---------------- f2: GN-affine + LeakyReLU + conv3d D (64->32) ----------------
__global__ void __launch_bounds__(256) k_f2(const float* __restrict__ x,
                                            const float* __restrict__ w,
                                            const float* __restrict__ b,
                                            float* __restrict__ out)
{
    __shared__ float ws[6144];           // [32oc][64ic][3t]
    __shared__ float As[128], Bs2[128];
    int tid = threadIdx.x;
    #pragma unroll 1
    for (int i = tid; i < 6144; i += 256) ws[i] = w[i];
    if (tid < 128){ As[tid]=g_A[tid]; Bs2[tid]=g_B[tid]; }
    __syncthreads();

    int n  = blockIdx.y; int bb = n / 24, d = n - bb*24;
    int lane = tid & 31, ocg = tid >> 5;         // oc = ocg*4..+3
    int hw0 = blockIdx.x * 256 + lane;

    float acc[4][8];
    #pragma unroll
    for (int j=0;j<4;j++){
        #pragma unroll
        for (int k=0;k<8;k++) acc[j][k]=0.f;
    }
    const float* sb = g_sf1 + bb*39321600;

    #pragma unroll 1
    for (int ic = 0; ic < 64; ic++) {
        float A = As[bb*64+ic], Bv = Bs2[bb*64+ic];
        float wr[4][3];
        #pragma unroll
        for (int j=0;j<4;j++){
            int oc = ocg*4+j;
            wr[j][0]=ws[oc*192+ic*3+0];
            wr[j][1]=ws[oc*192+ic*3+1];
            wr[j][2]=ws[oc*192+ic*3+2];
        }
        #pragma unroll
        for (int t=0;t<3;t++){
            int dd = d + t - 1;
            if (dd >= 0 && dd < 24){
                const float* sp = sb + ic*IMG + dd*HWSZ + hw0;
                #pragma unroll
                for (int k=0;k<8;k++){
                    float v = sp[k*32];
                    v = fmaf(A, v, Bv);
                    v = fmaxf(v, 0.2f*v);          // LeakyReLU(0.2)
                    #pragma unroll
                    for (int j=0;j<4;j++) acc[j][k] = fmaf(wr[j][t], v, acc[j][k]);
                }
            }
        }
    }

    #pragma unroll
    for (int j=0;j<4;j++){
        int oc = ocg*4+j;
        float bv = b[oc];
        int base = bb*BST + oc*IMG + d*HWSZ + hw0;
        #pragma unroll
        for (int k=0;k<8;k++)
            out[base + k*32] = __ldg(x + base + k*32) + acc[j][k] + bv;
    }
}

// ---------------- gate conv: full [x_d, h] conv via tf32 mma (256 thr) ----------
// grid (100, 4, 2): z=0 -> U gate (g_u), z=1 -> R gate (g_rh)
// K = 576 as 4 ic-chunks of 16: chunks 0,1 from x (W ic 0..31);
// chunks 2,3 from h (W ic 32..63).  Weight offset uses ch*16 (NOT input ic0).
__global__ void __launch_bounds__(256, 2)
k_gate(const float* __restrict__ x,
       const float* __restrict__ wu,
       const float* __restrict__ wr,
       const float* __restrict__ bu,
       const float* __restrict__ br,
       int ph, int s, int first)
{
    __shared__ uint32_t sIn[16*360];     // [16 ic][18 rows][stride 20] tf32
    __shared__ uint32_t sW[5184];        // [9 kk][32 oc][18 pad] (pads unread)

    int tid  = threadIdx.x;
    int tile = blockIdx.x;
    int tx = tile % 10, ty = tile / 10;
    int n = blockIdx.y;
    int z = blockIdx.z;                  // 0=U, 1=R
    int bb = n & 1;
    int d  = (n < 2) ? s : 23 - s;

    const float* Wp = (z == 0) ? wu : wr;

    int w2   = (tid >> 5) * 2;           // warp's two image rows in tile
    int lane = tid & 31;
    int lq   = lane >> 2;                // 0..7
    int lr   = lane & 3;                 // 0..3

    float c[2][4][4];
    #pragma unroll
    for (int mt=0;mt<2;mt++)
        #pragma unroll
        for (int nt=0;nt<4;nt++)
            #pragma unroll
            for (int k=0;k<4;k++) c[mt][nt][k]=0.f;

    int nch = first ? 2 : 4;             // h == 0 at step 0
    #pragma unroll 1
    for (int ch = 0; ch < nch; ch++){
        if (ch) __syncthreads();
        const float* src; int ics, ibase, ic0;
        if (ch < 2){ src = x;       ics = IMG;  ibase = bb*BST + d*HWSZ; ic0 = ch*16; }
        else       { src = g_h[ph]; ics = HWSZ; ibase = n*819200;        ic0 = (ch-2)*16; }
        #pragma unroll 1
        for (int idx = tid; idx < 5184; idx += 256){
            int ic = idx / 324; int rem = idx - ic*324;
            int r = rem / 18;   int c2 = rem - r*18;
            int gy = ty*16 - 1 + r, gx = tx*16 - 1 + c2;
            float v = 0.f;
            if ((unsigned)gy < 160u && (unsigned)gx < 160u)
                v = __ldg(src + ibase + (ic0+ic)*ics + gy*160 + gx);
            sIn[ic*360 + r*20 + c2] = tf32cvt(v);
        }
        // weights: global [32oc][64ic][3][3] -> sW[kk][oc][18];
        // concat channel index = ch*16 + ic  (x: 0..31, h: 32..63)
        #pragma unroll 1
        for (int idx = tid; idx < 4608; idx += 256){
            int oc = idx / 144; int rem = idx - oc*144;
            int ic = rem / 9;   int kk = rem - ic*9;
            sW[kk*576 + oc*18 + ic] =
                tf32cvt(__ldg(Wp + oc*576 + (ch*16+ic)*9 + kk));
        }
        __syncthreads();

        #pragma unroll
        for (int kk = 0; kk < 9; kk++){
            int dy = kk / 3, dx = kk - dy*3;
            #pragma unroll
            for (int h = 0; h < 2; h++){
                uint32_t a[2][4];
                int abase0 = (h*8 + lr)*360 + (w2 + dy)*20 + lq + dx;
                #pragma unroll
                for (int mt=0;mt<2;mt++){
                    int ab = abase0 + mt*20;
                    a[mt][0] = sIn[ab];
                    a[mt][1] = sIn[ab + 8];
                    a[mt][2] = sIn[ab + 4*360];
                    a[mt][3] = sIn[ab + 4*360 + 8];
                }
                #pragma unroll
                for (int nt=0;nt<4;nt++){
                    int bidx = kk*576 + (nt*8 + lq)*18 + h*8 + lr;
                    uint32_t b0 = sW[bidx], b1 = sW[bidx + 4];
                    mma_tf32(c[0][nt], a[0], b0, b1);
                    mma_tf32(c[1][nt], a[1], b0, b1);
                }
            }
        }
    }

    // epilogue
    #pragma unroll
    for (int mt=0;mt<2;mt++){
        int oy = ty*16 + w2 + mt;
        #pragma unroll
        for (int nt=0;nt<4;nt++){
            #pragma unroll
            for (int cr=0;cr<4;cr++){
                int xx = lq + ((cr >> 1) << 3);
                int oc = nt*8 + lr*2 + (cr & 1);
                int hw = oy*160 + tx*16 + xx;
                float a = c[mt][nt][cr];
                int hidx = n*819200 + oc*HWSZ + hw;
                if (z == 0){
                    g_u[hidx] = sigm(a + __ldg(bu + oc));
                } else {
                    float r2 = sigm(a + __ldg(br + oc));
                    float hv = first ? 0.f : g_h[ph][hidx];
                    g_rh[hidx] = r2 * hv;
                }
            }
        }
    }
}

// ---------------- candidate + update (256 threads) ----------------
// Full conv over [x_d, rh]; h' = (1-u)h + u*tanh(conv+b)
__global__ void __launch_bounds__(256, 2)
k_cand(const float* __restrict__ x,
       const float* __restrict__ wo,
       const float* __restrict__ bo,
       int ph, int s, int first)
{
    __shared__ uint32_t sIn[16*360];
    __shared__ uint32_t sW[5184];

    int tid  = threadIdx.x;
    int tile = blockIdx.x;
    int tx = tile % 10, ty = tile / 10;
    int n = blockIdx.y;
    int bb = n & 1;
    int d  = (n < 2) ? s : 23 - s;

    int w2   = (tid >> 5) * 2;
    int lane = tid & 31;
    int lq   = lane >> 2;
    int lr   = lane & 3;

    float c[2][4][4];
    #pragma unroll
    for (int mt=0;mt<2;mt++)
        #pragma unroll
        for (int nt=0;nt<4;nt++)
            #pragma unroll
            for (int k=0;k<4;k++) c[mt][nt][k]=0.f;

    int nch = first ? 2 : 4;             // rh == 0 at step 0
    #pragma unroll 1
    for (int ch = 0; ch < nch; ch++){
        if (ch) __syncthreads();
        const float* src; int ics, ibase, ic0;
        if (ch < 2){ src = x;    ics = IMG;  ibase = bb*BST + d*HWSZ; ic0 = ch*16; }
        else       { src = g_rh; ics = HWSZ; ibase = n*819200;        ic0 = (ch-2)*16; }
        #pragma unroll 1
        for (int idx = tid; idx < 5184; idx += 256){
            int ic = idx / 324; int rem = idx - ic*324;
            int r = rem / 18;   int c2 = rem - r*18;
            int gy = ty*16 - 1 + r, gx = tx*16 - 1 + c2;
            float v = 0.f;
            if ((unsigned)gy < 160u && (unsigned)gx < 160u)
                v = __ldg(src + ibase + (ic0+ic)*ics + gy*160 + gx);
            sIn[ic*360 + r*20 + c2] = tf32cvt(v);
        }
        // weight concat channel index = ch*16 + ic (x: 0..31, rh: 32..63)
        #pragma unroll 1
        for (int idx = tid; idx < 4608; idx += 256){
            int oc = idx / 144; int rem = idx - oc*144;
            int ic = rem / 9;   int kk = rem - ic*9;
            sW[kk*576 + oc*18 + ic] =
                tf32cvt(__ldg(wo + oc*576 + (ch*16+ic)*9 + kk));
        }
        __syncthreads();

        #pragma unroll
        for (int kk = 0; kk < 9; kk++){
            int dy = kk / 3, dx = kk - dy*3;
            #pragma unroll
            for (int h = 0; h < 2; h++){
                uint32_t a[2][4];
                int abase0 = (h*8 + lr)*360 + (w2 + dy)*20 + lq + dx;
                #pragma unroll
                for (int mt=0;mt<2;mt++){
                    int ab = abase0 + mt*20;
                    a[mt][0] = sIn[ab];
                    a[mt][1] = sIn[ab + 8];
                    a[mt][2] = sIn[ab + 4*360];
                    a[mt][3] = sIn[ab + 4*360 + 8];
                }
                #pragma unroll
                for (int nt=0;nt<4;nt++){
                    int bidx = kk*576 + (nt*8 + lq)*18 + h*8 + lr;
                    uint32_t b0 = sW[bidx], b1 = sW[bidx + 4];
                    mma_tf32(c[0][nt], a[0], b0, b1);
                    mma_tf32(c[1][nt], a[1], b0, b1);
                }
            }
        }
    }

    // epilogue: GRU update
    #pragma unroll
    for (int mt=0;mt<2;mt++){
        int oy = ty*16 + w2 + mt;
        #pragma unroll
        for (int nt=0;nt<4;nt++){
            #pragma unroll
            for (int cr=0;cr<4;cr++){
                int xx = lq + ((cr >> 1) << 3);
                int oc = nt*8 + lr*2 + (cr & 1);
                int hw = oy*160 + tx*16 + xx;
                float a = c[mt][nt][cr];
                int pidx = bb*BST + oc*IMG + d*HWSZ + hw;
                int hidx = n*819200 + oc*HWSZ + hw;
                float cd = tanhf(a + __ldg(bo + oc));
                float u  = g_u[hidx];
                float hp = first ? 0.f : g_h[ph][hidx];
                float hn = (1.f - u)*hp + u*cd;
                g_h[ph^1][hidx] = hn;
                g_hist[n >= 2 ? 1 : 0][pidx] = hn;
            }
        }
    }
}

// ---------------- merge: out += hist_f + hist_b (vectorized) ----------------
__global__ void __launch_bounds__(256) k_merge(float* __restrict__ out)
{
    int i = blockIdx.x * 256 + threadIdx.x;      // float4 index, 9830400 total
    float4 o = reinterpret_cast<float4*>(out)[i];
    float4 f = reinterpret_cast<const float4*>(g_hist[0])[i];
    float4 b = reinterpret_cast<const float4*>(g_hist[1])[i];
    o.x += f.x + b.x;  o.y += f.y + b.y;
    o.z += f.z + b.z;  o.w += f.w + b.w;
    reinterpret_cast<float4*>(out)[i] = o;
}

// ---------------- host ----------------
extern "C" void kernel_launch(void* const* d_in, const int* in_sizes, int n_in,
                              void* d_out, int out_size)
{
    const float* x    = (const float*)d_in[0];
    const float* w_f1 = (const float*)d_in[1];
    const float* b_f1 = (const float*)d_in[2];
    const float* gn_g = (const float*)d_in[3];
    const float* gn_b = (const float*)d_in[4];
    const float* w_f2 = (const float*)d_in[5];
    const float* b_f2 = (const float*)d_in[6];
    const float* w_u  = (const float*)d_in[7];
    const float* b_u  = (const float*)d_in[8];
    const float* w_r  = (const float*)d_in[9];
    const float* b_r  = (const float*)d_in[10];
    const float* w_o  = (const float*)d_in[11];
    const float* b_o  = (const float*)d_in[12];
    float* out = (float*)d_out;

    cudaStream_t s1;
    cudaStreamCreateWithFlags(&s1, cudaStreamNonBlocking);
    cudaEvent_t eFork, eJoin;
    cudaEventCreateWithFlags(&eFork, cudaEventDisableTiming);
    cudaEventCreateWithFlags(&eJoin, cudaEventDisableTiming);

    cudaEventRecord(eFork, 0);
    cudaStreamWaitEvent(s1, eFork, 0);

    // ---- GRU scan on main stream ----
    dim3 gGate(100, 4, 2), gCand(100, 4);
    for (int s = 0; s < 24; s++){
        int ph = (s + 1) & 1;       // read g_h[ph], write g_h[ph^1]
        int first = (s == 0) ? 1 : 0;
        k_gate<<<gGate, 256>>>(x, w_u, w_r, b_u, b_r, ph, s, first);
        k_cand<<<gCand, 256>>>(x, w_o, b_o, ph, s, first);
    }

    // ---- slice_flow on s1 (concurrent): writes out = x + slice_features ----
    dim3 gImg(100, 48);
    k_gz<<<1, 32, 0, s1>>>();
    k_f1<<<gImg, 256, 0, s1>>>(x, w_f1, b_f1);
    k_gnfin<<<1, 128, 0, s1>>>(gn_g, gn_b);
    k_f2<<<gImg, 256, 0, s1>>>(x, w_f2, b_f2, out);

    // join and merge: out += hist_f + hist_b
    cudaEventRecord(eJoin, s1);
    cudaStreamWaitEvent(0, eJoin, 0);
    k_merge<<<38400, 256>>>(out);
}